// round 17
// baseline (speedup 1.0000x reference)
#include <cuda_runtime.h>
#include <cuda_fp16.h>
#include <cstdint>
#include <math.h>

#define Bc 2
#define Nc 2048
#define Dc 1024
#define Hc 16
#define E3 192   // kqv col space per head: k(0:64), q(64:128), v(128:192)

__device__ __half g_kqv16[Bc * Hc * Nc * 128];  // [b,h,n,128]: k(0:64), q(64:128)
__device__ __half g_v16[Bc * Hc * 64 * Nc];     // [b,h,dim,n]  (V transposed)
__device__ __half g_sa16[Bc * Nc * Dc];         // [b,n,d]
__device__ __half g_WkT16[Hc * E3 * Dc];        // W_kqv as [c=h*192+e][k]
__device__ __half g_x16[Bc * Nc * Dc];          // x
__device__ __half g_Wp16[Dc * Dc];              // W_proj

__device__ __forceinline__ uint32_t smem_to_u32(const void* p) {
    uint32_t a;
    asm("{ .reg .u64 t; cvta.to.shared.u64 t, %1; cvt.u32.u64 %0, t; }"
        : "=r"(a) : "l"(p));
    return a;
}
__device__ __forceinline__ uint32_t h2_as_u32(__half2 h) {
    return *reinterpret_cast<uint32_t*>(&h);
}
__device__ __forceinline__ void mma_f16(float* c, const uint32_t* a, const uint32_t* b) {
    asm volatile(
        "mma.sync.aligned.m16n8k16.row.col.f32.f16.f16.f32 "
        "{%0,%1,%2,%3}, {%4,%5,%6,%7}, {%8,%9}, {%0,%1,%2,%3};"
        : "+f"(c[0]), "+f"(c[1]), "+f"(c[2]), "+f"(c[3])
        : "r"(a[0]), "r"(a[1]), "r"(a[2]), "r"(a[3]), "r"(b[0]), "r"(b[1]));
}
#define CP16(dst_u32, src_ptr) \
    asm volatile("cp.async.cg.shared.global [%0], [%1], 16;" \
        :: "r"(dst_u32), "l"(src_ptr))
#define CP_COMMIT() asm volatile("cp.async.commit_group;" ::: "memory")
#define CP_WAIT1()  asm volatile("cp.async.wait_group 1;" ::: "memory")
#define CP_WAIT0()  asm volatile("cp.async.wait_group 0;" ::: "memory")

// ---------------------------------------------------------------------------
// Fused pre-pass: convert x, Wp to half; transpose+convert Wk.
// ---------------------------------------------------------------------------
__global__ __launch_bounds__(256) void prepass(
    const float* __restrict__ x, const float* __restrict__ Wp,
    const float* __restrict__ Wk)
{
    __shared__ float tile[32][33];
    const int bid = blockIdx.x;
    if (bid < 4096) {
        const int i = (bid * 256 + threadIdx.x) * 4;
        float4 v = *(const float4*)&x[i];
        __half2* dst = (__half2*)&g_x16[i];
        dst[0] = __floats2half2_rn(v.x, v.y);
        dst[1] = __floats2half2_rn(v.z, v.w);
    } else if (bid < 5120) {
        const int i = ((bid - 4096) * 256 + threadIdx.x) * 4;
        float4 v = *(const float4*)&Wp[i];
        __half2* dst = (__half2*)&g_Wp16[i];
        dst[0] = __floats2half2_rn(v.x, v.y);
        dst[1] = __floats2half2_rn(v.z, v.w);
    } else {
        const int idx = bid - 5120;          // 0..3071
        const int e0 = (idx % 6) * 32;
        const int k0 = ((idx / 6) % 32) * 32;
        const int h  = idx / 192;
        const float* src = Wk + (size_t)h * Dc * E3;
        __half* dst = g_WkT16 + (size_t)h * E3 * Dc;
        const int tx = threadIdx.x & 31, ty0 = threadIdx.x >> 5;
        #pragma unroll
        for (int i = 0; i < 4; i++) {
            int ty = ty0 + i * 8;
            tile[ty][tx] = src[(size_t)(k0 + ty) * E3 + e0 + tx];
        }
        __syncthreads();
        #pragma unroll
        for (int i = 0; i < 4; i++) {
            int ty = ty0 + i * 8;
            dst[(size_t)(e0 + ty) * Dc + k0 + tx] = __float2half_rn(tile[tx][ty]);
        }
    }
}

// ---------------------------------------------------------------------------
// fp16 mma.sync GEMM (round-16, known good): 128x128 CTA tile, 4 warps (2x2),
// warp tile 64x64, K-slab 64 halfs, 2-stage cp.async.
// ---------------------------------------------------------------------------
#define GS2 36
#define GSTGW (128 * GS2 * 2)
#define GSMEM (2 * GSTGW * 4)
template<bool KQV>
__global__ __launch_bounds__(128) void gemm_mma(
    const float* __restrict__ bias, float* __restrict__ outp)
{
    const __half* __restrict__ A    = KQV ? (const __half*)g_x16 : (const __half*)g_sa16;
    const __half* __restrict__ Bmat = KQV ? (const __half*)g_WkT16 : (const __half*)g_Wp16;

    extern __shared__ uint32_t smw[];
    const uint32_t su = smem_to_u32(smw);
    const int t = threadIdx.x;
    const int lane = t & 31;
    const int warp = t >> 5;
    const int mbase = (warp >> 1) * 64;
    const int nbase = (warp & 1) * 64;
    const int grp = lane >> 2;
    const int ctg = lane & 3;
    const int c0 = blockIdx.x * 128;
    const int r0 = blockIdx.y * 128;

    auto issue_slab = [&](int s, int buf) {
        const int k0 = s * 64;
        #pragma unroll
        for (int it = 0; it < 8; it++) {
            const int task = it * 128 + t;
            const int row = task >> 3, ch = task & 7;
            CP16(su + (uint32_t)(buf * GSTGW + row * GS2 + ch * 4) * 4,
                 &A[(size_t)(r0 + row) * Dc + k0 + ch * 8]);
            CP16(su + (uint32_t)(buf * GSTGW + 128 * GS2 + row * GS2 + ch * 4) * 4,
                 &Bmat[(size_t)(c0 + row) * Dc + k0 + ch * 8]);
        }
    };

    issue_slab(0, 0); CP_COMMIT();
    issue_slab(1, 1); CP_COMMIT();

    float C[4][8][4];
    #pragma unroll
    for (int i = 0; i < 4; i++)
        #pragma unroll
        for (int j = 0; j < 8; j++)
            #pragma unroll
            for (int k = 0; k < 4; k++) C[i][j][k] = 0.f;

    for (int s = 0; s < 16; s++) {
        if (s == 15) { CP_WAIT0(); } else { CP_WAIT1(); }
        __syncthreads();
        const uint32_t* As = smw + (s & 1) * GSTGW;
        const uint32_t* Bs = As + 128 * GS2;
        #pragma unroll
        for (int kk = 0; kk < 4; kk++) {
            const int kof = kk * 8 + ctg;
            uint32_t af[4][4];
            #pragma unroll
            for (int tm = 0; tm < 4; tm++) {
                const int m = mbase + tm * 16 + grp;
                af[tm][0] = As[m * GS2 + kof];
                af[tm][1] = As[(m + 8) * GS2 + kof];
                af[tm][2] = As[m * GS2 + kof + 4];
                af[tm][3] = As[(m + 8) * GS2 + kof + 4];
            }
            #pragma unroll
            for (int tn = 0; tn < 8; tn++) {
                const int n = nbase + tn * 8 + grp;
                uint32_t bf[2];
                bf[0] = Bs[n * GS2 + kof];
                bf[1] = Bs[n * GS2 + kof + 4];
                #pragma unroll
                for (int tm = 0; tm < 4; tm++)
                    mma_f16(C[tm][tn], af[tm], bf);
            }
        }
        __syncthreads();
        if (s + 2 < 16) issue_slab(s + 2, s & 1);
        CP_COMMIT();
    }

    #pragma unroll
    for (int tm = 0; tm < 4; tm++) {
        #pragma unroll
        for (int tn = 0; tn < 8; tn++) {
            const int c = c0 + nbase + tn * 8 + ctg * 2;
            const float bs0 = bias[c], bs1 = bias[c + 1];
            #pragma unroll
            for (int half_ = 0; half_ < 2; half_++) {
                const int row = r0 + mbase + tm * 16 + grp + half_ * 8;
                float ox = C[tm][tn][half_ * 2 + 0] + bs0;
                float oy = C[tm][tn][half_ * 2 + 1] + bs1;
                if (KQV) {
                    const int h = c / E3;
                    const int e = c - h * E3;
                    const int b = row >> 11, n = row & 2047;
                    if (e < 128) {
                        *(__half2*)&g_kqv16[(((size_t)(b * Hc + h)) * Nc + n) * 128 + e] =
                            __floats2half2_rn(ox, oy);
                    } else {
                        const int d = e - 128;
                        __half* vp = g_v16 + (((size_t)(b * Hc + h)) * 64 + d) * Nc + n;
                        vp[0]  = __float2half_rn(ox);
                        vp[Nc] = __float2half_rn(oy);
                    }
                } else {
                    float2 o; o.x = ox; o.y = oy;
                    *(float2*)&outp[(size_t)row * Dc + c] = o;
                }
            }
        }
    }
}

// ---------------------------------------------------------------------------
// fp16 attention: flash, q-tile 64 (4 warps x 16 rows), K-TILE 128 keys.
// Softmax/barrier/staging overhead per key halved vs 64-key tiles.
// cp.async staging. Paired scheduling (31-p, p): uniform 17 k-tiles per CTA.
// Smem words: Qs@0 (64x36), Ks@2304 (128x36), VT@6912 (64x68), Ps@11264 (64x68)
//  = 15616 words = 62464 B.
// ---------------------------------------------------------------------------
#define AS2 36
#define VS2 68
#define ATTN_SMEM 62464
__global__ __launch_bounds__(128) void attn_mma()
{
    extern __shared__ uint32_t smw[];
    uint32_t* Qs = smw;
    uint32_t* Ks = smw + 2304;
    uint32_t* VT = smw + 6912;
    uint32_t* Ps = smw + 11264;
    const uint32_t su = smem_to_u32(smw);

    const int t = threadIdx.x;
    const int lane = t & 31, warp = t >> 5;
    const int grp = lane >> 2, ctg = lane & 3;
    const int mb = warp * 16;
    const int bh = blockIdx.y;
    const int b = bh >> 4, h = bh & 15;
    const int p = blockIdx.x;          // 0..15
    const __half* kqbase = g_kqv16 + (size_t)bh * Nc * 128;
    const __half* vbase  = g_v16 + (size_t)bh * 64 * Nc;

    #pragma unroll 1
    for (int seg = 0; seg < 2; seg++) {
        const int qt = seg == 0 ? (31 - p) : p;
        const int q0 = qt * 64;
        const int ntk = (qt + 2) >> 1;     // 128-key tiles needed

        __syncthreads();
        // stage Q [qrow][dim]
        #pragma unroll
        for (int it = 0; it < 4; it++) {
            const int task = it * 128 + t;
            const int row = task >> 3, ch = task & 7;
            *(uint4*)&Qs[row * AS2 + ch * 4] =
                *(const uint4*)&kqbase[(size_t)(q0 + row) * 128 + 64 + ch * 8];
        }
        __syncthreads();
        uint32_t qf[4][4];
        #pragma unroll
        for (int kk = 0; kk < 4; kk++) {
            qf[kk][0] = Qs[(mb + grp) * AS2 + kk * 8 + ctg];
            qf[kk][1] = Qs[(mb + grp + 8) * AS2 + kk * 8 + ctg];
            qf[kk][2] = Qs[(mb + grp) * AS2 + kk * 8 + ctg + 4];
            qf[kk][3] = Qs[(mb + grp + 8) * AS2 + kk * 8 + ctg + 4];
        }

        float OC[8][4];
        #pragma unroll
        for (int i = 0; i < 8; i++)
            #pragma unroll
            for (int j = 0; j < 4; j++) OC[i][j] = 0.f;
        float m0 = -1e30f, m1 = -1e30f, l0 = 0.f, l1 = 0.f;
        const int gr0 = q0 + mb + grp, gr1 = gr0 + 8;

        for (int kt = 0; kt < ntk; kt++) {
            const int k0 = kt * 128;
            __syncthreads();
            // cp.async stage K [key][dim]: 128 rows x 8 chunks
            #pragma unroll
            for (int it = 0; it < 8; it++) {
                const int task = it * 128 + t;
                const int row = task >> 3, ch = task & 7;
                CP16(su + (uint32_t)(2304 + row * AS2 + ch * 4) * 4,
                     &kqbase[(size_t)(k0 + row) * 128 + ch * 8]);
            }
            // cp.async stage V^T [dim][key]: 64 rows x 16 chunks
            #pragma unroll
            for (int it = 0; it < 8; it++) {
                const int task = it * 128 + t;
                const int row = task >> 4, ch = task & 15;
                CP16(su + (uint32_t)(6912 + row * VS2 + ch * 4) * 4,
                     &vbase[(size_t)row * Nc + k0 + ch * 8]);
            }
            CP_COMMIT(); CP_WAIT0();
            __syncthreads();

            // S = Q K^T over 128 keys, then scale 1/8
            float SC[16][4];
            #pragma unroll
            for (int i = 0; i < 16; i++)
                #pragma unroll
                for (int j = 0; j < 4; j++) SC[i][j] = 0.f;
            #pragma unroll
            for (int kk = 0; kk < 4; kk++) {
                #pragma unroll
                for (int nt = 0; nt < 16; nt++) {
                    uint32_t bf[2];
                    bf[0] = Ks[(nt * 8 + grp) * AS2 + kk * 8 + ctg];
                    bf[1] = Ks[(nt * 8 + grp) * AS2 + kk * 8 + ctg + 4];
                    mma_f16(SC[nt], qf[kk], bf);
                }
            }
            #pragma unroll
            for (int i = 0; i < 16; i++)
                #pragma unroll
                for (int j = 0; j < 4; j++) SC[i][j] *= 0.125f;

            // causal mask (global indices) on last tile
            if (kt == ntk - 1) {
                #pragma unroll
                for (int nt = 0; nt < 16; nt++) {
                    const int col = k0 + nt * 8 + 2 * ctg;
                    if (col > gr0)     SC[nt][0] = -1e30f;
                    if (col + 1 > gr0) SC[nt][1] = -1e30f;
                    if (col > gr1)     SC[nt][2] = -1e30f;
                    if (col + 1 > gr1) SC[nt][3] = -1e30f;
                }
            }

            // online softmax
            float tm0 = -1e30f, tm1 = -1e30f;
            #pragma unroll
            for (int nt = 0; nt < 16; nt++) {
                tm0 = fmaxf(tm0, fmaxf(SC[nt][0], SC[nt][1]));
                tm1 = fmaxf(tm1, fmaxf(SC[nt][2], SC[nt][3]));
            }
            tm0 = fmaxf(tm0, __shfl_xor_sync(0xffffffffu, tm0, 1));
            tm0 = fmaxf(tm0, __shfl_xor_sync(0xffffffffu, tm0, 2));
            tm1 = fmaxf(tm1, __shfl_xor_sync(0xffffffffu, tm1, 1));
            tm1 = fmaxf(tm1, __shfl_xor_sync(0xffffffffu, tm1, 2));
            const float mn0 = fmaxf(m0, tm0), mn1 = fmaxf(m1, tm1);
            const float corr0 = __expf(m0 - mn0), corr1 = __expf(m1 - mn1);
            m0 = mn0; m1 = mn1;
            float s0 = 0.f, s1 = 0.f;
            #pragma unroll
            for (int nt = 0; nt < 16; nt++) {
                SC[nt][0] = __expf(SC[nt][0] - mn0); s0 += SC[nt][0];
                SC[nt][1] = __expf(SC[nt][1] - mn0); s0 += SC[nt][1];
                SC[nt][2] = __expf(SC[nt][2] - mn1); s1 += SC[nt][2];
                SC[nt][3] = __expf(SC[nt][3] - mn1); s1 += SC[nt][3];
            }
            s0 += __shfl_xor_sync(0xffffffffu, s0, 1);
            s0 += __shfl_xor_sync(0xffffffffu, s0, 2);
            s1 += __shfl_xor_sync(0xffffffffu, s1, 1);
            s1 += __shfl_xor_sync(0xffffffffu, s1, 2);
            l0 = l0 * corr0 + s0;
            l1 = l1 * corr1 + s1;
            #pragma unroll
            for (int nt = 0; nt < 8; nt++) {
                OC[nt][0] *= corr0; OC[nt][1] *= corr0;
                OC[nt][2] *= corr1; OC[nt][3] *= corr1;
            }

            // P -> warp-private band of Ps (keys packed half2 along row)
            #pragma unroll
            for (int nt = 0; nt < 16; nt++) {
                Ps[(mb + grp) * VS2 + nt * 4 + ctg] =
                    h2_as_u32(__floats2half2_rn(SC[nt][0], SC[nt][1]));
                Ps[(mb + grp + 8) * VS2 + nt * 4 + ctg] =
                    h2_as_u32(__floats2half2_rn(SC[nt][2], SC[nt][3]));
            }
            __syncwarp();

            // O += P V : A = P[qrow][key] (8 k16 chunks), B = VT[dim][key]
            #pragma unroll
            for (int kc = 0; kc < 8; kc++) {
                uint32_t af[4];
                af[0] = Ps[(mb + grp) * VS2 + kc * 8 + ctg];
                af[1] = Ps[(mb + grp + 8) * VS2 + kc * 8 + ctg];
                af[2] = Ps[(mb + grp) * VS2 + kc * 8 + ctg + 4];
                af[3] = Ps[(mb + grp + 8) * VS2 + kc * 8 + ctg + 4];
                #pragma unroll
                for (int dt = 0; dt < 8; dt++) {
                    uint32_t bf[2];
                    bf[0] = VT[(dt * 8 + grp) * VS2 + kc * 8 + ctg];
                    bf[1] = VT[(dt * 8 + grp) * VS2 + kc * 8 + ctg + 4];
                    mma_f16(OC[dt], af, bf);
                }
            }
        }

        const float inv0 = 1.f / l0, inv1 = 1.f / l1;
        const int r0g = b * Nc + q0 + mb + grp;
        #pragma unroll
        for (int dt = 0; dt < 8; dt++) {
            const int c = h * 64 + dt * 8 + 2 * ctg;
            *(__half2*)&g_sa16[(size_t)r0g * Dc + c] =
                __floats2half2_rn(OC[dt][0] * inv0, OC[dt][1] * inv0);
            *(__half2*)&g_sa16[(size_t)(r0g + 8) * Dc + c] =
                __floats2half2_rn(OC[dt][2] * inv1, OC[dt][3] * inv1);
        }
    }
}

extern "C" void kernel_launch(void* const* d_in, const int* in_sizes, int n_in,
                              void* d_out, int out_size)
{
    const float* x  = (const float*)d_in[0];
    const float* Wk = (const float*)d_in[1];
    const float* bk = (const float*)d_in[2];
    const float* Wp = (const float*)d_in[3];
    const float* bp = (const float*)d_in[4];
    float* out = (float*)d_out;

    cudaFuncSetAttribute((const void*)gemm_mma<true>,
                         cudaFuncAttributeMaxDynamicSharedMemorySize, GSMEM);
    cudaFuncSetAttribute((const void*)gemm_mma<false>,
                         cudaFuncAttributeMaxDynamicSharedMemorySize, GSMEM);
    cudaFuncSetAttribute((const void*)attn_mma,
                         cudaFuncAttributeMaxDynamicSharedMemorySize, ATTN_SMEM);

    prepass<<<8192, 256>>>(x, Wp, Wk);

    gemm_mma<true><<<dim3(24, 32), 128, GSMEM>>>(bk, nullptr);

    attn_mma<<<dim3(16, 32), 128, ATTN_SMEM>>>();

    gemm_mma<false><<<dim3(8, 32), 128, GSMEM>>>(bp, out);
}